// round 6
// baseline (speedup 1.0000x reference)
#include <cuda_runtime.h>
#include <stdint.h>

// ---------------------------------------------------------------------------
// BoltzmannGateSTE: keep top-k (k = int(n/e)) by |x|, zero the rest.
// ONE streamed pass with a speculative threshold window + exact verification.
// R6: occupancy/MLP fix — 1184 blocks x 256 thr (64 warps/SM), 4-deep load
// unroll, 24KB smem/block so 8 blocks/SM co-reside (grid barrier safe).
// ---------------------------------------------------------------------------

#define NBINS   (1u << 20)
#define NSUP    1024
#define NCOARSE 4096
#define LISTCAP (1 << 22)      // 4M entries (expected ~1.11M)
#define CAPB    2560           // per-block staging (expected ~940/block)
#define NBLK    1184           // 148 SMs * 8
#define NTHR    256
#define NTOT    (NBLK * NTHR)
#define WLO_N   0x3F600000u    // bits(0.875f)
#define WSPAN_N (1u << 20)     // window = exactly 2^20 ulp-groups
#define WHI_N   (WLO_N + WSPAN_N)   // bits(0.9375f)

__device__ __align__(16) unsigned g_fine[NBINS];
__device__ unsigned g_super[NSUP];
__device__ unsigned g_coarse[NCOARSE];
__device__ unsigned g_A;
__device__ unsigned g_listcnt;
__device__ unsigned g_overflow;
__device__ unsigned g_mode;
__device__ unsigned g_krem;
__device__ unsigned g_wlo;
__device__ unsigned g_tbits;
__device__ unsigned g_bar_cnt;
__device__ volatile unsigned g_bar_sense;
__device__ uint2    g_list[LISTCAP];

// -------- prologue: zero ALL scratch + barrier state (runs each replay) ----
__global__ void zero_all() {
    int idx = blockIdx.x * blockDim.x + threadIdx.x;
    int stride = gridDim.x * blockDim.x;
    uint4 z = make_uint4(0, 0, 0, 0);
    uint4* f4 = (uint4*)g_fine;
    for (unsigned i = idx; i < NBINS / 4; i += stride) f4[i] = z;
    for (int i = idx; i < NCOARSE; i += stride) g_coarse[i] = 0;
    for (int i = idx; i < NSUP; i += stride) g_super[i] = 0;
    if (idx == 0) {
        g_A = 0; g_listcnt = 0; g_overflow = 0; g_mode = 0;
        g_bar_cnt = 0; g_bar_sense = 0;
    }
}

// -------- software grid barrier (sense-reversing; state reset by prologue) -
__device__ __forceinline__ void gbar(unsigned* sense_smem) {
    __syncthreads();
    if (threadIdx.x == 0) {
        unsigned s = *sense_smem ^ 1u;
        *sense_smem = s;
        __threadfence();
        if (atomicAdd(&g_bar_cnt, 1u) == NBLK - 1u) {
            g_bar_cnt = 0u;
            __threadfence();
            g_bar_sense = s;
        } else {
            while (g_bar_sense != s) __nanosleep(64);
            __threadfence();
        }
    }
    __syncthreads();
}

// -------- block0 helper: descending-rank search over 1024 counts -----------
// src: 1024 counts. Finds bin where cumulative-from-top first reaches krem.
// Writes bin -> svar[3], residual -> svar[4]. 256 threads, 4 bins each.
__device__ void scan1024_desc(const unsigned* __restrict__ src, unsigned krem,
                              unsigned* scratch, unsigned* svar) {
    const int t = threadIdx.x;
    unsigned c0 = src[4 * t], c1 = src[4 * t + 1];
    unsigned c2 = src[4 * t + 2], c3 = src[4 * t + 3];
    scratch[t] = c0 + c1 + c2 + c3;
    __syncthreads();
    for (int off = 1; off < NTHR; off <<= 1) {
        unsigned add = (t + off < NTHR) ? scratch[t + off] : 0u;
        __syncthreads();
        scratch[t] += add;
        __syncthreads();
    }
    unsigned cum = (t < NTHR - 1) ? scratch[t + 1] : 0u;  // total strictly above
    unsigned cc[4] = {c0, c1, c2, c3};
    #pragma unroll
    for (int j = 3; j >= 0; j--) {
        unsigned prev = cum;
        cum += cc[j];
        if (cum >= krem && prev < krem) { svar[3] = 4u * t + j; svar[4] = krem - prev; }
    }
    __syncthreads();
}

__global__ void __launch_bounds__(NTHR, 8)
boltzmann_all(const float4* __restrict__ x, float4* __restrict__ out,
              int n4, int rem, unsigned k)
{
    __shared__ unsigned scratch[1024];   // 4KB: reductions / scans
    __shared__ uint2    sbuf[CAPB];      // 20KB: window staging
    __shared__ unsigned svar[8];         // 0:scnt 1:sbase 2:sense 3:idx 4:rem2

    const int tid  = threadIdx.x;
    const int gtid = blockIdx.x * NTHR + tid;
    const float* xs = (const float*)x;
    float* outs = (float*)out;

    if (tid < 8) svar[tid] = 0;
    __syncthreads();

    // ============ P1: stream read -> speculative write + count + stage =====
    unsigned cntHi = 0;
#define PROC(v, i_) { \
    unsigned r0 = __float_as_uint(v.x), r1 = __float_as_uint(v.y); \
    unsigned r2 = __float_as_uint(v.z), r3 = __float_as_uint(v.w); \
    unsigned u0 = r0 & 0x7FFFFFFFu, u1 = r1 & 0x7FFFFFFFu; \
    unsigned u2 = r2 & 0x7FFFFFFFu, u3 = r3 & 0x7FFFFFFFu; \
    float4 o; \
    o.x = (u0 >= WHI_N) ? v.x : 0.0f; \
    o.y = (u1 >= WHI_N) ? v.y : 0.0f; \
    o.z = (u2 >= WHI_N) ? v.z : 0.0f; \
    o.w = (u3 >= WHI_N) ? v.w : 0.0f; \
    cntHi += (u0 >= WHI_N) + (u1 >= WHI_N) + (u2 >= WHI_N) + (u3 >= WHI_N); \
    __stcs(&out[i_], o); \
    unsigned d0 = u0 - WLO_N, d1 = u1 - WLO_N, d2 = u2 - WLO_N, d3 = u3 - WLO_N; \
    if ((d0 < WSPAN_N) | (d1 < WSPAN_N) | (d2 < WSPAN_N) | (d3 < WSPAN_N)) { \
        unsigned eb = (unsigned)(i_) * 4u; \
        if (d0 < WSPAN_N) { unsigned p = atomicAdd(&svar[0], 1u); if (p < CAPB) { sbuf[p].x = eb;      sbuf[p].y = r0; } } \
        if (d1 < WSPAN_N) { unsigned p = atomicAdd(&svar[0], 1u); if (p < CAPB) { sbuf[p].x = eb + 1u; sbuf[p].y = r1; } } \
        if (d2 < WSPAN_N) { unsigned p = atomicAdd(&svar[0], 1u); if (p < CAPB) { sbuf[p].x = eb + 2u; sbuf[p].y = r2; } } \
        if (d3 < WSPAN_N) { unsigned p = atomicAdd(&svar[0], 1u); if (p < CAPB) { sbuf[p].x = eb + 3u; sbuf[p].y = r3; } } \
    } \
}
    {
        int i = gtid;
        for (; i + 3 * NTOT < n4; i += 4 * NTOT) {
            float4 v0 = __ldcs(&x[i]);
            float4 v1 = __ldcs(&x[i + NTOT]);
            float4 v2 = __ldcs(&x[i + 2 * NTOT]);
            float4 v3 = __ldcs(&x[i + 3 * NTOT]);
            PROC(v0, i);
            PROC(v1, i + NTOT);
            PROC(v2, i + 2 * NTOT);
            PROC(v3, i + 3 * NTOT);
        }
        for (; i < n4; i += NTOT) {
            float4 v = __ldcs(&x[i]);
            PROC(v, i);
        }
    }
#undef PROC
    if (gtid < rem) {   // scalar tail
        float f = xs[n4 * 4 + gtid];
        unsigned raw = __float_as_uint(f);
        unsigned u = raw & 0x7FFFFFFFu;
        cntHi += (u >= WHI_N);
        outs[n4 * 4 + gtid] = (u >= WHI_N) ? f : 0.0f;
        if (u - WLO_N < WSPAN_N) {
            unsigned p = atomicAdd(&svar[0], 1u);
            if (p < CAPB) { sbuf[p].x = (unsigned)(n4 * 4 + gtid); sbuf[p].y = raw; }
        }
    }

    // block-reduce cntHi -> g_A ; reserve list space
    scratch[tid] = cntHi;
    __syncthreads();
    for (int off = NTHR / 2; off > 0; off >>= 1) {
        if (tid < off) scratch[tid] += scratch[tid + off];
        __syncthreads();
    }
    if (tid == 0) {
        if (scratch[0]) atomicAdd(&g_A, scratch[0]);
        unsigned c = svar[0];
        if (c > CAPB) { c = CAPB; g_overflow = 1u; }
        unsigned base = atomicAdd(&g_listcnt, c);
        if (base + c > LISTCAP) g_overflow = 1u;
        svar[0] = c;
        svar[1] = base;
    }
    __syncthreads();
    {   // flush staging -> list + window histogram
        unsigned c = svar[0], base = svar[1];
        for (unsigned j = tid; j < c; j += NTHR) {
            uint2 e = sbuf[j];
            if (base + j < LISTCAP) g_list[base + j] = e;
            atomicAdd(&g_fine[(e.y & 0x7FFFFFFFu) - WLO_N], 1u);
        }
    }
    gbar(&svar[2]);   // ---- barrier

    // ============ P2: exact verification ===================================
    if (blockIdx.x == 0 && tid == 0) {
        unsigned A = g_A, cnt = g_listcnt, ov = g_overflow;
        unsigned mode = 1u;
        if (!ov && A < k && (k - A) <= cnt) {
            mode = 0u; g_krem = k - A; g_wlo = WLO_N;
        }
        g_mode = mode;
    }
    gbar(&svar[2]);   // ---- barrier

    const unsigned mode = g_mode;
    unsigned cnt = g_listcnt;
    if (cnt > LISTCAP) cnt = LISTCAP;

    // ============ Fallback: full exact radix select (never hot) ============
    if (mode) {
        uint4 z = make_uint4(0, 0, 0, 0);
        uint4* f4 = (uint4*)g_fine;
        for (unsigned i = gtid; i < NBINS / 4; i += NTOT) f4[i] = z;
        for (int i = gtid; i < NCOARSE; i += NTOT) g_coarse[i] = 0;
        gbar(&svar[2]);
        for (int i = gtid; i < n4; i += NTOT) {
            float4 v = x[i];
            atomicAdd(&g_coarse[(__float_as_uint(v.x) & 0x7FFFFFFFu) >> 19], 1u);
            atomicAdd(&g_coarse[(__float_as_uint(v.y) & 0x7FFFFFFFu) >> 19], 1u);
            atomicAdd(&g_coarse[(__float_as_uint(v.z) & 0x7FFFFFFFu) >> 19], 1u);
            atomicAdd(&g_coarse[(__float_as_uint(v.w) & 0x7FFFFFFFu) >> 19], 1u);
        }
        if (gtid < rem)
            atomicAdd(&g_coarse[(__float_as_uint(xs[n4 * 4 + gtid]) & 0x7FFFFFFFu) >> 19], 1u);
        gbar(&svar[2]);

        if (blockIdx.x == 0) {   // coarse scan: 16 buckets per thread
            unsigned c[16], sum = 0;
            #pragma unroll
            for (int j = 0; j < 16; j++) { c[j] = g_coarse[tid * 16 + j]; sum += c[j]; }
            scratch[tid] = sum;
            __syncthreads();
            for (int off = 1; off < NTHR; off <<= 1) {
                unsigned add = (tid + off < NTHR) ? scratch[tid + off] : 0u;
                __syncthreads();
                scratch[tid] += add;
                __syncthreads();
            }
            unsigned cum = (tid < NTHR - 1) ? scratch[tid + 1] : 0u;
            #pragma unroll
            for (int j = 15; j >= 0; j--) {
                unsigned prev = cum;
                cum += c[j];
                if (cum >= k && prev < k) {
                    g_wlo  = ((unsigned)(tid * 16 + j)) << 19;
                    g_krem = k - prev;
                }
            }
        }
        gbar(&svar[2]);

        const unsigned wlo = g_wlo;
        for (int i = gtid; i < n4; i += NTOT) {
            float4 v = x[i];
            unsigned u0 = __float_as_uint(v.x) & 0x7FFFFFFFu;
            unsigned u1 = __float_as_uint(v.y) & 0x7FFFFFFFu;
            unsigned u2 = __float_as_uint(v.z) & 0x7FFFFFFFu;
            unsigned u3 = __float_as_uint(v.w) & 0x7FFFFFFFu;
            if (u0 - wlo < (1u << 19)) atomicAdd(&g_fine[u0 - wlo], 1u);
            if (u1 - wlo < (1u << 19)) atomicAdd(&g_fine[u1 - wlo], 1u);
            if (u2 - wlo < (1u << 19)) atomicAdd(&g_fine[u2 - wlo], 1u);
            if (u3 - wlo < (1u << 19)) atomicAdd(&g_fine[u3 - wlo], 1u);
        }
        if (gtid < rem) {
            unsigned u = __float_as_uint(xs[n4 * 4 + gtid]) & 0x7FFFFFFFu;
            if (u - wlo < (1u << 19)) atomicAdd(&g_fine[u - wlo], 1u);
        }
        gbar(&svar[2]);
    }

    // ============ P4a: reduce 2^20 bins -> 1024 supers (warp per super) ====
    {
        int w = blockIdx.x * (NTHR / 32) + (tid >> 5);
        int lane = tid & 31;
        if (w < NSUP) {
            const uint4* p = (const uint4*)(g_fine + (unsigned)w * 1024u);
            unsigned s = 0;
            #pragma unroll
            for (int j = 0; j < 8; j++) {
                uint4 q = p[lane + 32 * j];
                s += q.x + q.y + q.z + q.w;
            }
            #pragma unroll
            for (int off = 16; off > 0; off >>= 1)
                s += __shfl_down_sync(0xFFFFFFFFu, s, off);
            if (lane == 0) g_super[w] = s;
        }
    }
    gbar(&svar[2]);   // ---- barrier

    // ============ P4b: block0 resolves exact threshold bits ================
    if (blockIdx.x == 0) {
        scan1024_desc(g_super, g_krem, scratch, svar);          // -> super sb
        unsigned sb = svar[3], krem2 = svar[4];
        scan1024_desc(g_fine + sb * 1024u, krem2, scratch, svar); // -> bin
        if (tid == 0) g_tbits = g_wlo + sb * 1024u + svar[3];
    }
    gbar(&svar[2]);   // ---- barrier

    // ============ P5: fixup (normal) or full re-mask (fallback) ============
    const unsigned tb = g_tbits;
    if (!mode) {
        for (unsigned j = (unsigned)gtid; j < cnt; j += NTOT) {
            uint2 e = g_list[j];
            if ((e.y & 0x7FFFFFFFu) >= tb) outs[e.x] = __uint_as_float(e.y);
        }
    } else {
        for (int i = gtid; i < n4; i += NTOT) {
            float4 v = x[i];
            v.x = ((__float_as_uint(v.x) & 0x7FFFFFFFu) >= tb) ? v.x : 0.0f;
            v.y = ((__float_as_uint(v.y) & 0x7FFFFFFFu) >= tb) ? v.y : 0.0f;
            v.z = ((__float_as_uint(v.z) & 0x7FFFFFFFu) >= tb) ? v.z : 0.0f;
            v.w = ((__float_as_uint(v.w) & 0x7FFFFFFFu) >= tb) ? v.w : 0.0f;
            out[i] = v;
        }
        for (int g = gtid; g < rem; g += NTOT) {
            float f = xs[n4 * 4 + g];
            outs[n4 * 4 + g] = ((__float_as_uint(f) & 0x7FFFFFFFu) >= tb) ? f : 0.0f;
        }
    }
}

__global__ void copy_all(const float4* __restrict__ x, float4* __restrict__ out, int n4) {
    int idx = blockIdx.x * blockDim.x + threadIdx.x;
    int stride = gridDim.x * blockDim.x;
    for (int i = idx; i < n4; i += stride) out[i] = x[i];
}

extern "C" void kernel_launch(void* const* d_in, const int* in_sizes, int n_in,
                              void* d_out, int out_size) {
    const float* x = (const float*)d_in[0];
    float* out = (float*)d_out;
    int n = in_sizes[0];

    // k = max(1, int(n * (1.0/e))) — bit-exact replication of the Python.
    const double FRACTION = 1.0 / 2.718281828459045235360287;
    long long kll = (long long)((double)n * FRACTION);
    if (kll < 1) kll = 1;

    int n4 = n >> 2;
    int rem = n & 3;

    if (kll >= (long long)n) {
        copy_all<<<1024, 256>>>((const float4*)x, (float4*)out, n4);
        return;
    }

    zero_all<<<NBLK, NTHR>>>();
    boltzmann_all<<<NBLK, NTHR>>>((const float4*)x, (float4*)out,
                                  n4, rem, (unsigned)kll);
}

// round 7
// speedup vs baseline: 1.0915x; 1.0915x over previous
#include <cuda_runtime.h>
#include <stdint.h>

// ---------------------------------------------------------------------------
// BoltzmannGateSTE: keep top-k (k = int(n/e)) by |x|, zero the rest.
// ONE streamed pass with a speculative threshold window + exact verification.
// R7: P1 loop de-unrolled (single float4 load+store per iteration) — R6's
// 4-deep unroll under a 32-reg cap spilled to local memory and flooded the
// L1tex queue (DRAM% 34.9). R1 evidence: this grid + simple loop = 62% DRAM.
// ---------------------------------------------------------------------------

#define NBINS   (1u << 20)
#define NSUP    1024
#define NCOARSE 4096
#define LISTCAP (1 << 22)      // 4M entries (expected ~1.11M)
#define CAPB    2560           // per-block staging (expected ~934/block)
#define NBLK    1184           // 148 SMs * 8
#define NTHR    256
#define NTOT    (NBLK * NTHR)
#define WLO_N   0x3F600000u    // bits(0.875f)
#define WSPAN_N (1u << 20)     // window = exactly 2^20 ulp-groups
#define WHI_N   (WLO_N + WSPAN_N)   // bits(0.9375f)

__device__ __align__(16) unsigned g_fine[NBINS];
__device__ unsigned g_super[NSUP];
__device__ unsigned g_coarse[NCOARSE];
__device__ unsigned g_A;
__device__ unsigned g_listcnt;
__device__ unsigned g_overflow;
__device__ unsigned g_mode;
__device__ unsigned g_krem;
__device__ unsigned g_wlo;
__device__ unsigned g_tbits;
__device__ unsigned g_bar_cnt;
__device__ volatile unsigned g_bar_sense;
__device__ uint2    g_list[LISTCAP];

// -------- prologue: zero ALL scratch + barrier state (runs each replay) ----
__global__ void zero_all() {
    int idx = blockIdx.x * blockDim.x + threadIdx.x;
    int stride = gridDim.x * blockDim.x;
    uint4 z = make_uint4(0, 0, 0, 0);
    uint4* f4 = (uint4*)g_fine;
    for (unsigned i = idx; i < NBINS / 4; i += stride) f4[i] = z;
    for (int i = idx; i < NCOARSE; i += stride) g_coarse[i] = 0;
    for (int i = idx; i < NSUP; i += stride) g_super[i] = 0;
    if (idx == 0) {
        g_A = 0; g_listcnt = 0; g_overflow = 0; g_mode = 0;
        g_bar_cnt = 0; g_bar_sense = 0;
    }
}

// -------- software grid barrier (sense-reversing; state reset by prologue) -
__device__ __forceinline__ void gbar(unsigned* sense_smem) {
    __syncthreads();
    if (threadIdx.x == 0) {
        unsigned s = *sense_smem ^ 1u;
        *sense_smem = s;
        __threadfence();
        if (atomicAdd(&g_bar_cnt, 1u) == NBLK - 1u) {
            g_bar_cnt = 0u;
            __threadfence();
            g_bar_sense = s;
        } else {
            while (g_bar_sense != s) __nanosleep(64);
            __threadfence();
        }
    }
    __syncthreads();
}

// -------- block0 helper: descending-rank search over 1024 counts -----------
__device__ void scan1024_desc(const unsigned* __restrict__ src, unsigned krem,
                              unsigned* scratch, unsigned* svar) {
    const int t = threadIdx.x;
    unsigned c0 = src[4 * t], c1 = src[4 * t + 1];
    unsigned c2 = src[4 * t + 2], c3 = src[4 * t + 3];
    scratch[t] = c0 + c1 + c2 + c3;
    __syncthreads();
    for (int off = 1; off < NTHR; off <<= 1) {
        unsigned add = (t + off < NTHR) ? scratch[t + off] : 0u;
        __syncthreads();
        scratch[t] += add;
        __syncthreads();
    }
    unsigned cum = (t < NTHR - 1) ? scratch[t + 1] : 0u;  // total strictly above
    unsigned cc[4] = {c0, c1, c2, c3};
    #pragma unroll
    for (int j = 3; j >= 0; j--) {
        unsigned prev = cum;
        cum += cc[j];
        if (cum >= krem && prev < krem) { svar[3] = 4u * t + j; svar[4] = krem - prev; }
    }
    __syncthreads();
}

__global__ void __launch_bounds__(NTHR, 8)
boltzmann_all(const float4* __restrict__ x, float4* __restrict__ out,
              int n4, int rem, unsigned k)
{
    __shared__ unsigned scratch[1024];   // 4KB: reductions / scans
    __shared__ uint2    sbuf[CAPB];      // 20KB: window staging
    __shared__ unsigned svar[8];         // 0:scnt 1:sbase 2:sense 3:idx 4:rem2

    const int tid  = threadIdx.x;
    const int gtid = blockIdx.x * NTHR + tid;
    const float* xs = (const float*)x;
    float* outs = (float*)out;

    if (tid < 8) svar[tid] = 0;
    __syncthreads();

    // ============ P1: stream read -> speculative write + count + stage =====
    // ONE float4 load + ONE store per iteration; minimal live registers.
    unsigned cntHi = 0;
    for (int i = gtid; i < n4; i += NTOT) {
        float4 v = __ldcs(&x[i]);
        unsigned r0 = __float_as_uint(v.x), r1 = __float_as_uint(v.y);
        unsigned r2 = __float_as_uint(v.z), r3 = __float_as_uint(v.w);
        unsigned u0 = r0 & 0x7FFFFFFFu, u1 = r1 & 0x7FFFFFFFu;
        unsigned u2 = r2 & 0x7FFFFFFFu, u3 = r3 & 0x7FFFFFFFu;
        float4 o;
        o.x = (u0 >= WHI_N) ? v.x : 0.0f;
        o.y = (u1 >= WHI_N) ? v.y : 0.0f;
        o.z = (u2 >= WHI_N) ? v.z : 0.0f;
        o.w = (u3 >= WHI_N) ? v.w : 0.0f;
        cntHi += (u0 >= WHI_N) + (u1 >= WHI_N) + (u2 >= WHI_N) + (u3 >= WHI_N);
        __stcs(&out[i], o);
        unsigned d0 = u0 - WLO_N, d1 = u1 - WLO_N;
        unsigned d2 = u2 - WLO_N, d3 = u3 - WLO_N;
        if ((d0 < WSPAN_N) | (d1 < WSPAN_N) | (d2 < WSPAN_N) | (d3 < WSPAN_N)) {
            unsigned eb = (unsigned)i * 4u;
            if (d0 < WSPAN_N) { unsigned p = atomicAdd(&svar[0], 1u); if (p < CAPB) { sbuf[p].x = eb;      sbuf[p].y = r0; } }
            if (d1 < WSPAN_N) { unsigned p = atomicAdd(&svar[0], 1u); if (p < CAPB) { sbuf[p].x = eb + 1u; sbuf[p].y = r1; } }
            if (d2 < WSPAN_N) { unsigned p = atomicAdd(&svar[0], 1u); if (p < CAPB) { sbuf[p].x = eb + 2u; sbuf[p].y = r2; } }
            if (d3 < WSPAN_N) { unsigned p = atomicAdd(&svar[0], 1u); if (p < CAPB) { sbuf[p].x = eb + 3u; sbuf[p].y = r3; } }
        }
    }
    if (gtid < rem) {   // scalar tail
        float f = xs[n4 * 4 + gtid];
        unsigned raw = __float_as_uint(f);
        unsigned u = raw & 0x7FFFFFFFu;
        cntHi += (u >= WHI_N);
        outs[n4 * 4 + gtid] = (u >= WHI_N) ? f : 0.0f;
        if (u - WLO_N < WSPAN_N) {
            unsigned p = atomicAdd(&svar[0], 1u);
            if (p < CAPB) { sbuf[p].x = (unsigned)(n4 * 4 + gtid); sbuf[p].y = raw; }
        }
    }

    // block-reduce cntHi -> g_A ; reserve list space
    scratch[tid] = cntHi;
    __syncthreads();
    for (int off = NTHR / 2; off > 0; off >>= 1) {
        if (tid < off) scratch[tid] += scratch[tid + off];
        __syncthreads();
    }
    if (tid == 0) {
        if (scratch[0]) atomicAdd(&g_A, scratch[0]);
        unsigned c = svar[0];
        if (c > CAPB) { c = CAPB; g_overflow = 1u; }
        unsigned base = atomicAdd(&g_listcnt, c);
        if (base + c > LISTCAP) g_overflow = 1u;
        svar[0] = c;
        svar[1] = base;
    }
    __syncthreads();
    {   // flush staging -> list + window histogram
        unsigned c = svar[0], base = svar[1];
        for (unsigned j = tid; j < c; j += NTHR) {
            uint2 e = sbuf[j];
            if (base + j < LISTCAP) g_list[base + j] = e;
            atomicAdd(&g_fine[(e.y & 0x7FFFFFFFu) - WLO_N], 1u);
        }
    }
    gbar(&svar[2]);   // ---- barrier

    // ============ P2: exact verification ===================================
    if (blockIdx.x == 0 && tid == 0) {
        unsigned A = g_A, cnt = g_listcnt, ov = g_overflow;
        unsigned mode = 1u;
        if (!ov && A < k && (k - A) <= cnt) {
            mode = 0u; g_krem = k - A; g_wlo = WLO_N;
        }
        g_mode = mode;
    }
    gbar(&svar[2]);   // ---- barrier

    const unsigned mode = g_mode;
    unsigned cnt = g_listcnt;
    if (cnt > LISTCAP) cnt = LISTCAP;

    // ============ Fallback: full exact radix select (never hot) ============
    if (mode) {
        uint4 z = make_uint4(0, 0, 0, 0);
        uint4* f4 = (uint4*)g_fine;
        for (unsigned i = gtid; i < NBINS / 4; i += NTOT) f4[i] = z;
        for (int i = gtid; i < NCOARSE; i += NTOT) g_coarse[i] = 0;
        gbar(&svar[2]);
        for (int i = gtid; i < n4; i += NTOT) {
            float4 v = x[i];
            atomicAdd(&g_coarse[(__float_as_uint(v.x) & 0x7FFFFFFFu) >> 19], 1u);
            atomicAdd(&g_coarse[(__float_as_uint(v.y) & 0x7FFFFFFFu) >> 19], 1u);
            atomicAdd(&g_coarse[(__float_as_uint(v.z) & 0x7FFFFFFFu) >> 19], 1u);
            atomicAdd(&g_coarse[(__float_as_uint(v.w) & 0x7FFFFFFFu) >> 19], 1u);
        }
        if (gtid < rem)
            atomicAdd(&g_coarse[(__float_as_uint(xs[n4 * 4 + gtid]) & 0x7FFFFFFFu) >> 19], 1u);
        gbar(&svar[2]);

        if (blockIdx.x == 0) {   // coarse scan: 16 buckets per thread
            unsigned c[16], sum = 0;
            #pragma unroll
            for (int j = 0; j < 16; j++) { c[j] = g_coarse[tid * 16 + j]; sum += c[j]; }
            scratch[tid] = sum;
            __syncthreads();
            for (int off = 1; off < NTHR; off <<= 1) {
                unsigned add = (tid + off < NTHR) ? scratch[tid + off] : 0u;
                __syncthreads();
                scratch[tid] += add;
                __syncthreads();
            }
            unsigned cum = (tid < NTHR - 1) ? scratch[tid + 1] : 0u;
            #pragma unroll
            for (int j = 15; j >= 0; j--) {
                unsigned prev = cum;
                cum += c[j];
                if (cum >= k && prev < k) {
                    g_wlo  = ((unsigned)(tid * 16 + j)) << 19;
                    g_krem = k - prev;
                }
            }
        }
        gbar(&svar[2]);

        const unsigned wlo = g_wlo;
        for (int i = gtid; i < n4; i += NTOT) {
            float4 v = x[i];
            unsigned u0 = __float_as_uint(v.x) & 0x7FFFFFFFu;
            unsigned u1 = __float_as_uint(v.y) & 0x7FFFFFFFu;
            unsigned u2 = __float_as_uint(v.z) & 0x7FFFFFFFu;
            unsigned u3 = __float_as_uint(v.w) & 0x7FFFFFFFu;
            if (u0 - wlo < (1u << 19)) atomicAdd(&g_fine[u0 - wlo], 1u);
            if (u1 - wlo < (1u << 19)) atomicAdd(&g_fine[u1 - wlo], 1u);
            if (u2 - wlo < (1u << 19)) atomicAdd(&g_fine[u2 - wlo], 1u);
            if (u3 - wlo < (1u << 19)) atomicAdd(&g_fine[u3 - wlo], 1u);
        }
        if (gtid < rem) {
            unsigned u = __float_as_uint(xs[n4 * 4 + gtid]) & 0x7FFFFFFFu;
            if (u - wlo < (1u << 19)) atomicAdd(&g_fine[u - wlo], 1u);
        }
        gbar(&svar[2]);
    }

    // ============ P4a: reduce 2^20 bins -> 1024 supers (warp per super) ====
    {
        int w = blockIdx.x * (NTHR / 32) + (tid >> 5);
        int lane = tid & 31;
        if (w < NSUP) {
            const uint4* p = (const uint4*)(g_fine + (unsigned)w * 1024u);
            unsigned s = 0;
            #pragma unroll
            for (int j = 0; j < 8; j++) {
                uint4 q = p[lane + 32 * j];
                s += q.x + q.y + q.z + q.w;
            }
            #pragma unroll
            for (int off = 16; off > 0; off >>= 1)
                s += __shfl_down_sync(0xFFFFFFFFu, s, off);
            if (lane == 0) g_super[w] = s;
        }
    }
    gbar(&svar[2]);   // ---- barrier

    // ============ P4b: block0 resolves exact threshold bits ================
    if (blockIdx.x == 0) {
        scan1024_desc(g_super, g_krem, scratch, svar);            // -> super sb
        unsigned sb = svar[3], krem2 = svar[4];
        scan1024_desc(g_fine + sb * 1024u, krem2, scratch, svar); // -> bin
        if (tid == 0) g_tbits = g_wlo + sb * 1024u + svar[3];
    }
    gbar(&svar[2]);   // ---- barrier

    // ============ P5: fixup (normal) or full re-mask (fallback) ============
    const unsigned tb = g_tbits;
    if (!mode) {
        for (unsigned j = (unsigned)gtid; j < cnt; j += NTOT) {
            uint2 e = g_list[j];
            if ((e.y & 0x7FFFFFFFu) >= tb) outs[e.x] = __uint_as_float(e.y);
        }
    } else {
        for (int i = gtid; i < n4; i += NTOT) {
            float4 v = x[i];
            v.x = ((__float_as_uint(v.x) & 0x7FFFFFFFu) >= tb) ? v.x : 0.0f;
            v.y = ((__float_as_uint(v.y) & 0x7FFFFFFFu) >= tb) ? v.y : 0.0f;
            v.z = ((__float_as_uint(v.z) & 0x7FFFFFFFu) >= tb) ? v.z : 0.0f;
            v.w = ((__float_as_uint(v.w) & 0x7FFFFFFFu) >= tb) ? v.w : 0.0f;
            out[i] = v;
        }
        for (int g = gtid; g < rem; g += NTOT) {
            float f = xs[n4 * 4 + g];
            outs[n4 * 4 + g] = ((__float_as_uint(f) & 0x7FFFFFFFu) >= tb) ? f : 0.0f;
        }
    }
}

__global__ void copy_all(const float4* __restrict__ x, float4* __restrict__ out, int n4) {
    int idx = blockIdx.x * blockDim.x + threadIdx.x;
    int stride = gridDim.x * blockDim.x;
    for (int i = idx; i < n4; i += stride) out[i] = x[i];
}

extern "C" void kernel_launch(void* const* d_in, const int* in_sizes, int n_in,
                              void* d_out, int out_size) {
    const float* x = (const float*)d_in[0];
    float* out = (float*)d_out;
    int n = in_sizes[0];

    // k = max(1, int(n * (1.0/e))) — bit-exact replication of the Python.
    const double FRACTION = 1.0 / 2.718281828459045235360287;
    long long kll = (long long)((double)n * FRACTION);
    if (kll < 1) kll = 1;

    int n4 = n >> 2;
    int rem = n & 3;

    if (kll >= (long long)n) {
        copy_all<<<1024, 256>>>((const float4*)x, (float4*)out, n4);
        return;
    }

    zero_all<<<NBLK, NTHR>>>();
    boltzmann_all<<<NBLK, NTHR>>>((const float4*)x, (float4*)out,
                                  n4, rem, (unsigned)kll);
}

// round 8
// speedup vs baseline: 1.3259x; 1.2148x over previous
#include <cuda_runtime.h>
#include <stdint.h>

// ---------------------------------------------------------------------------
// BoltzmannGateSTE: keep top-k (k = int(n/e)) by |x|, zero the rest.
// R8: back to SPLIT kernels — R3's standalone fused pass ran 4.2 TB/s while
// the identical loop inside the persistent kernel ran ~3 TB/s (smem carveout
// + multiphase register pressure). Launch overhead measured ~1us/kernel.
//   K1 zero_all:   zero 2MB hist + counters
//   K2 fused_p1:   read x once -> speculative out, stage window elems to
//                  list + window hist; LAST block verifies (ticket).
//   K3 fb_all:     exact radix-select fallback (no-op unless verify failed)
//   K4 supers_scan: 1024 super-sums; last block double-scan -> exact tbits
//   K5 fixup:      scatter keepers from list (or full re-mask in fallback)
// ---------------------------------------------------------------------------

#define NBINS   (1u << 20)
#define NSUP    1024
#define NCOARSE 4096
#define LISTCAP (1 << 22)      // 4M entries (expected ~1.11M)
#define CAPB    2048           // per-block staging (expected ~1081/block)
#define GRID    1024
#define BLK     256
#define STRIDE  (GRID * BLK)
#define FBGRID  444
#define WLO_N   0x3F600000u    // bits(0.875f)
#define WSPAN_N (1u << 20)     // window = exactly 2^20 ulp-groups
#define WHI_N   (WLO_N + WSPAN_N)   // bits(0.9375f)

__device__ __align__(16) unsigned g_fine[NBINS];
__device__ unsigned g_super[NSUP];
__device__ unsigned g_coarse[NCOARSE];
__device__ unsigned g_A;
__device__ unsigned g_listcnt;
__device__ unsigned g_overflow;
__device__ unsigned g_mode;
__device__ unsigned g_krem;
__device__ unsigned g_wlo;
__device__ unsigned g_tbits;
__device__ unsigned g_done1;       // ticket for K2 verification
__device__ unsigned g_done2;       // ticket for K4 scan
__device__ unsigned g_fb_cnt;      // fallback grid barrier
__device__ volatile unsigned g_fb_sense;
__device__ uint2    g_list[LISTCAP];

// ---------------- K1: zero scratch (runs each replay) ----------------------
__global__ void zero_all() {
    int idx = blockIdx.x * blockDim.x + threadIdx.x;
    int stride = gridDim.x * blockDim.x;
    uint4 z = make_uint4(0, 0, 0, 0);
    uint4* f4 = (uint4*)g_fine;
    for (unsigned i = idx; i < NBINS / 4; i += stride) f4[i] = z;
    for (int i = idx; i < NCOARSE; i += stride) g_coarse[i] = 0;
    for (int i = idx; i < NSUP; i += stride) g_super[i] = 0;
    if (idx == 0) {
        g_A = 0; g_listcnt = 0; g_overflow = 0; g_mode = 0;
        g_done1 = 0; g_done2 = 0; g_fb_cnt = 0; g_fb_sense = 0;
    }
}

// ---------------- K2: fused streaming pass + last-block verify -------------
__global__ void __launch_bounds__(BLK)
fused_p1(const float4* __restrict__ x, float4* __restrict__ out,
         int n4, int rem, unsigned k)
{
    __shared__ uint2 sbuf[CAPB];          // 16KB staging
    __shared__ unsigned scratch[BLK];     // 1KB reduce
    __shared__ unsigned svar[4];          // 0:scnt 1:sbase
    const int tid = threadIdx.x;
    const int gtid = blockIdx.x * BLK + tid;
    const float* xs = (const float*)x;
    float* outs = (float*)out;

    if (tid == 0) svar[0] = 0;
    __syncthreads();

    unsigned cntHi = 0;
#define DO1(f, eidx, odst) { \
    unsigned raw = __float_as_uint(f); \
    unsigned u = raw & 0x7FFFFFFFu; \
    odst = (u >= WHI_N) ? f : 0.0f; \
    cntHi += (u >= WHI_N); \
    if (u - WLO_N < WSPAN_N) { \
        unsigned p = atomicAdd(&svar[0], 1u); \
        if (p < CAPB) { sbuf[p].x = (eidx); sbuf[p].y = raw; } \
    } \
}
#define DO4(vv, fi) { \
    float4 o; \
    unsigned eb = (unsigned)(fi) * 4u; \
    DO1(vv.x, eb + 0u, o.x); \
    DO1(vv.y, eb + 1u, o.y); \
    DO1(vv.z, eb + 2u, o.z); \
    DO1(vv.w, eb + 3u, o.w); \
    __stcs(&out[fi], o); \
}
    {
        int i = gtid;
        for (; i + STRIDE < n4; i += 2 * STRIDE) {
            float4 v0 = __ldcs(&x[i]);
            float4 v1 = __ldcs(&x[i + STRIDE]);
            DO4(v0, i);
            DO4(v1, i + STRIDE);
        }
        for (; i < n4; i += STRIDE) {
            float4 v = __ldcs(&x[i]);
            DO4(v, i);
        }
    }
#undef DO4
#undef DO1
    if (gtid < rem) {   // scalar tail
        float f = xs[n4 * 4 + gtid];
        unsigned raw = __float_as_uint(f);
        unsigned u = raw & 0x7FFFFFFFu;
        cntHi += (u >= WHI_N);
        outs[n4 * 4 + gtid] = (u >= WHI_N) ? f : 0.0f;
        if (u - WLO_N < WSPAN_N) {
            unsigned p = atomicAdd(&svar[0], 1u);
            if (p < CAPB) { sbuf[p].x = (unsigned)(n4 * 4 + gtid); sbuf[p].y = raw; }
        }
    }

    // block-reduce cntHi; reserve list space
    scratch[tid] = cntHi;
    __syncthreads();
    for (int off = BLK / 2; off > 0; off >>= 1) {
        if (tid < off) scratch[tid] += scratch[tid + off];
        __syncthreads();
    }
    if (tid == 0) {
        if (scratch[0]) atomicAdd(&g_A, scratch[0]);
        unsigned c = svar[0];
        if (c > CAPB) { c = CAPB; g_overflow = 1u; }
        unsigned base = atomicAdd(&g_listcnt, c);
        if (base + c > LISTCAP) g_overflow = 1u;
        svar[0] = c;
        svar[1] = base;
    }
    __syncthreads();
    {   // flush staging -> list + window histogram
        unsigned c = svar[0], base = svar[1];
        for (unsigned j = tid; j < c; j += BLK) {
            uint2 e = sbuf[j];
            if (base + j < LISTCAP) g_list[base + j] = e;
            atomicAdd(&g_fine[(e.y & 0x7FFFFFFFu) - WLO_N], 1u);
        }
    }
    // last block out performs verification
    __syncthreads();
    __threadfence();
    if (tid == 0) {
        if (atomicAdd(&g_done1, 1u) == GRID - 1u) {
            unsigned A = g_A, cnt = g_listcnt, ov = g_overflow;
            unsigned mode = 1u;
            if (!ov && A < k && (k - A) <= cnt) {
                mode = 0u; g_krem = k - A; g_wlo = WLO_N;
            }
            g_mode = mode;
        }
    }
}

// ---------------- K3: exact fallback (no-op when verification passed) ------
__device__ __forceinline__ void fb_bar() {
    __syncthreads();
    __shared__ unsigned s_s;
    if (threadIdx.x == 0) {
        unsigned s = g_fb_sense ^ 1u;   // all blocks agree: sense flips per barrier
        __threadfence();
        if (atomicAdd(&g_fb_cnt, 1u) == FBGRID - 1u) {
            g_fb_cnt = 0u;
            __threadfence();
            g_fb_sense = s;
        } else {
            while (g_fb_sense != s) __nanosleep(64);
            __threadfence();
        }
        s_s = 0;
    }
    __syncthreads();
}

__global__ void __launch_bounds__(BLK)
fb_all(const float4* __restrict__ x, int n4, int rem, unsigned k)
{
    if (g_mode == 0u) return;
    __shared__ unsigned scratch[BLK];
    const int tid = threadIdx.x;
    const int gtid = blockIdx.x * BLK + tid;
    const int FTOT = FBGRID * BLK;
    const float* xs = (const float*)x;

    // zero stale window hist + build coarse hist (global atomics; cold path)
    uint4 z = make_uint4(0, 0, 0, 0);
    uint4* f4 = (uint4*)g_fine;
    for (unsigned i = gtid; i < NBINS / 4; i += FTOT) f4[i] = z;
    for (int i = gtid; i < n4; i += FTOT) {
        float4 v = x[i];
        atomicAdd(&g_coarse[(__float_as_uint(v.x) & 0x7FFFFFFFu) >> 19], 1u);
        atomicAdd(&g_coarse[(__float_as_uint(v.y) & 0x7FFFFFFFu) >> 19], 1u);
        atomicAdd(&g_coarse[(__float_as_uint(v.z) & 0x7FFFFFFFu) >> 19], 1u);
        atomicAdd(&g_coarse[(__float_as_uint(v.w) & 0x7FFFFFFFu) >> 19], 1u);
    }
    for (int g = gtid; g < rem; g += FTOT)
        atomicAdd(&g_coarse[(__float_as_uint(xs[n4 * 4 + g]) & 0x7FFFFFFFu) >> 19], 1u);
    fb_bar();

    if (blockIdx.x == 0) {   // coarse scan: 16 buckets per thread
        unsigned c[16], sum = 0;
        #pragma unroll
        for (int j = 0; j < 16; j++) { c[j] = g_coarse[tid * 16 + j]; sum += c[j]; }
        scratch[tid] = sum;
        __syncthreads();
        for (int off = 1; off < BLK; off <<= 1) {
            unsigned add = (tid + off < BLK) ? scratch[tid + off] : 0u;
            __syncthreads();
            scratch[tid] += add;
            __syncthreads();
        }
        unsigned cum = (tid < BLK - 1) ? scratch[tid + 1] : 0u;
        #pragma unroll
        for (int j = 15; j >= 0; j--) {
            unsigned prev = cum;
            cum += c[j];
            if (cum >= k && prev < k) {
                g_wlo  = ((unsigned)(tid * 16 + j)) << 19;
                g_krem = k - prev;
            }
        }
    }
    fb_bar();

    // fine hist over [wlo, wlo + 2^19)  (fills only low 2^19 bins; rest 0)
    const unsigned wlo = g_wlo;
    for (int i = gtid; i < n4; i += FTOT) {
        float4 v = x[i];
        unsigned u0 = __float_as_uint(v.x) & 0x7FFFFFFFu;
        unsigned u1 = __float_as_uint(v.y) & 0x7FFFFFFFu;
        unsigned u2 = __float_as_uint(v.z) & 0x7FFFFFFFu;
        unsigned u3 = __float_as_uint(v.w) & 0x7FFFFFFFu;
        if (u0 - wlo < (1u << 19)) atomicAdd(&g_fine[u0 - wlo], 1u);
        if (u1 - wlo < (1u << 19)) atomicAdd(&g_fine[u1 - wlo], 1u);
        if (u2 - wlo < (1u << 19)) atomicAdd(&g_fine[u2 - wlo], 1u);
        if (u3 - wlo < (1u << 19)) atomicAdd(&g_fine[u3 - wlo], 1u);
    }
    for (int g = gtid; g < rem; g += FTOT) {
        unsigned u = __float_as_uint(xs[n4 * 4 + g]) & 0x7FFFFFFFu;
        if (u - wlo < (1u << 19)) atomicAdd(&g_fine[u - wlo], 1u);
    }
}

// ---------------- K4: super sums + last-block double scan -> tbits ---------
__device__ void scan1024_desc(const unsigned* __restrict__ src, unsigned krem,
                              unsigned* scratch, unsigned* svar) {
    const int t = threadIdx.x;
    unsigned c0 = src[4 * t], c1 = src[4 * t + 1];
    unsigned c2 = src[4 * t + 2], c3 = src[4 * t + 3];
    scratch[t] = c0 + c1 + c2 + c3;
    __syncthreads();
    for (int off = 1; off < BLK; off <<= 1) {
        unsigned add = (t + off < BLK) ? scratch[t + off] : 0u;
        __syncthreads();
        scratch[t] += add;
        __syncthreads();
    }
    unsigned cum = (t < BLK - 1) ? scratch[t + 1] : 0u;
    unsigned cc[4] = {c0, c1, c2, c3};
    #pragma unroll
    for (int j = 3; j >= 0; j--) {
        unsigned prev = cum;
        cum += cc[j];
        if (cum >= krem && prev < krem) { svar[0] = 4u * t + j; svar[1] = krem - prev; }
    }
    __syncthreads();
}

__global__ void __launch_bounds__(BLK)
supers_scan()
{
    __shared__ unsigned scratch[BLK];
    __shared__ unsigned svar[4];
    const int tid = threadIdx.x;
    // 128 blocks x 8 warps: warp w sums super (blockIdx*8 + warp)
    int w = blockIdx.x * (BLK / 32) + (tid >> 5);
    int lane = tid & 31;
    if (w < NSUP) {
        const uint4* p = (const uint4*)(g_fine + (unsigned)w * 1024u);
        unsigned s = 0;
        #pragma unroll
        for (int j = 0; j < 8; j++) {
            uint4 q = p[lane + 32 * j];
            s += q.x + q.y + q.z + q.w;
        }
        #pragma unroll
        for (int off = 16; off > 0; off >>= 1)
            s += __shfl_down_sync(0xFFFFFFFFu, s, off);
        if (lane == 0) g_super[w] = s;
    }
    // last block out does the scans
    __threadfence();
    __shared__ unsigned s_last;
    if (tid == 0) s_last = (atomicAdd(&g_done2, 1u) == (NSUP / (BLK / 32)) - 1u);
    __syncthreads();
    if (!s_last) return;

    scan1024_desc(g_super, g_krem, scratch, svar);            // -> super sb
    unsigned sb = svar[0], krem2 = svar[1];
    scan1024_desc(g_fine + sb * 1024u, krem2, scratch, svar); // -> bin
    if (tid == 0) g_tbits = g_wlo + sb * 1024u + svar[0];
}

// ---------------- K5: fixup (normal) or full re-mask (fallback) ------------
__global__ void __launch_bounds__(BLK)
fixup(const float4* __restrict__ x, float4* __restrict__ out, int n4, int rem)
{
    const unsigned tb = g_tbits;
    const int gtid = blockIdx.x * BLK + threadIdx.x;
    float* outs = (float*)out;
    const float* xs = (const float*)x;
    if (g_mode == 0u) {
        unsigned cnt = g_listcnt;
        if (cnt > LISTCAP) cnt = LISTCAP;
        for (unsigned j = (unsigned)gtid; j < cnt; j += STRIDE) {
            uint2 e = g_list[j];
            if ((e.y & 0x7FFFFFFFu) >= tb) outs[e.x] = __uint_as_float(e.y);
        }
    } else {
        for (int i = gtid; i < n4; i += STRIDE) {
            float4 v = x[i];
            v.x = ((__float_as_uint(v.x) & 0x7FFFFFFFu) >= tb) ? v.x : 0.0f;
            v.y = ((__float_as_uint(v.y) & 0x7FFFFFFFu) >= tb) ? v.y : 0.0f;
            v.z = ((__float_as_uint(v.z) & 0x7FFFFFFFu) >= tb) ? v.z : 0.0f;
            v.w = ((__float_as_uint(v.w) & 0x7FFFFFFFu) >= tb) ? v.w : 0.0f;
            out[i] = v;
        }
        for (int g = gtid; g < rem; g += STRIDE) {
            float f = xs[n4 * 4 + g];
            outs[n4 * 4 + g] = ((__float_as_uint(f) & 0x7FFFFFFFu) >= tb) ? f : 0.0f;
        }
    }
}

__global__ void copy_all(const float4* __restrict__ x, float4* __restrict__ out, int n4) {
    int idx = blockIdx.x * blockDim.x + threadIdx.x;
    int stride = gridDim.x * blockDim.x;
    for (int i = idx; i < n4; i += stride) out[i] = x[i];
}

extern "C" void kernel_launch(void* const* d_in, const int* in_sizes, int n_in,
                              void* d_out, int out_size) {
    const float* x = (const float*)d_in[0];
    float* out = (float*)d_out;
    int n = in_sizes[0];

    // k = max(1, int(n * (1.0/e))) — bit-exact replication of the Python.
    const double FRACTION = 1.0 / 2.718281828459045235360287;
    long long kll = (long long)((double)n * FRACTION);
    if (kll < 1) kll = 1;

    int n4 = n >> 2;
    int rem = n & 3;

    if (kll >= (long long)n) {
        copy_all<<<GRID, BLK>>>((const float4*)x, (float4*)out, n4);
        return;
    }
    unsigned k = (unsigned)kll;

    zero_all<<<GRID, BLK>>>();
    fused_p1<<<GRID, BLK>>>((const float4*)x, (float4*)out, n4, rem, k);
    fb_all<<<FBGRID, BLK>>>((const float4*)x, n4, rem, k);
    supers_scan<<<NSUP / (BLK / 32), BLK>>>();
    fixup<<<GRID, BLK>>>((const float4*)x, (float4*)out, n4, rem);
}